// round 15
// baseline (speedup 1.0000x reference)
#include <cuda_runtime.h>
#include <cuda_fp16.h>
#include <math.h>

// ---------------------------------------------------------------------------
// TOF PET forward projection with spatially sorted events.
//  K1: image-layout tiles (both orientations) + histogram zeroing.
//  K2: per-event params + locality key + histogram.
//  K3: exclusive prefix sum over 4096 buckets (one block).
//  K4: scatter params into sorted order (+ original event id).
//  K5: project — R8 loop, coalesced sorted params, out[eid] at the end.
// ---------------------------------------------------------------------------

#define PAD_W   384
#define PADX    40
#define PADY    40
#define NSAMP   256
#define INV_NSAMP (1.0f / 256.0f)
#define ZCUT    3.6f           // tail 2*Q(3.6) ~ 3.2e-4
#define SPLIT   8
#define EMAX    160000
#define NTILE   18
#define NKEY    4096           // 64 angle x 8 cx x 8 cy

struct __align__(8) h4 { __half2 lo, hi; };

__device__ h4 g_padh [PAD_W * PAD_W];   // (u,v) = (x,y)
__device__ h4 g_padhT[PAD_W * PAD_W];   // (u,v) = (y,x)

__device__ float4 g_tA[EMAX];   // params by event id (temp)
__device__ float4 g_tB[EMAX];
__device__ int    g_key[EMAX];
__device__ int    g_hist[NKEY];
__device__ int    g_off[NKEY];
__device__ float4 g_pA[EMAX];   // params in sorted order
__device__ float4 g_pB[EMAX];
__device__ int    g_eid[EMAX];  // sorted position -> original event id

// ---- K1: image tiles + hist zero ----
__global__ void tiles_kernel(const float* __restrict__ img,
                             const int* __restrict__ nxp,
                             const int* __restrict__ nyp)
{
    const int tid = threadIdx.x;
    const int blk = blockIdx.x;
    const int NTILES = NTILE * NTILE;

    if (blk >= NTILES) {                   // hist zeroing blocks
        const int k = (blk - NTILES) * 256 + tid;
        if (k < NKEY) g_hist[k] = 0;
        return;
    }

    const int nx = *nxp;
    const int ny = *nyp;
    __shared__ float sm[17][18];
    const int ty = blk / NTILE;
    const int tx = blk - ty * NTILE;
    const int ixs = -1 + tx * 16;
    const int iys = -1 + ty * 16;

    for (int k = tid; k < 17 * 17; k += 256) {
        const int r = k / 17;
        const int c = k - r * 17;
        const int y = iys + r;
        const int x = ixs + c;
        sm[r][c] = (x >= 0 && x < nx && y >= 0 && y < ny)
                   ? img[y * nx + x] : 0.0f;
    }
    __syncthreads();

    {
        const int ly = tid >> 4;
        const int lx = tid & 15;
        h4 o;
        o.lo = __floats2half2_rn(sm[ly][lx],     sm[ly + 1][lx]);
        o.hi = __floats2half2_rn(sm[ly][lx + 1], sm[ly + 1][lx + 1]);
        g_padh[(iys + ly + PADY) * PAD_W + (ixs + lx + PADX)] = o;
    }
    {
        const int lx = tid >> 4;
        const int ly = tid & 15;
        h4 o;
        o.lo = __floats2half2_rn(sm[ly][lx],     sm[ly][lx + 1]);
        o.hi = __floats2half2_rn(sm[ly + 1][lx], sm[ly + 1][lx + 1]);
        g_padhT[(ixs + lx + PADX) * PAD_W + (iys + ly + PADY)] = o;
    }
}

// ---- K2: params + key + histogram ----
__global__ void keys_kernel(const float* __restrict__ tof,
               const float* __restrict__ x1l, const float* __restrict__ y1l,
               const float* __restrict__ x1r, const float* __restrict__ y1r,
               const float* __restrict__ x2l, const float* __restrict__ y2l,
               const float* __restrict__ x2r, const float* __restrict__ y2r,
               const float* __restrict__ trp,
               const float* __restrict__ dxp, const float* __restrict__ dyp,
               const int* __restrict__ nxp, const int* __restrict__ nyp,
               int E)
{
    const int e = blockIdx.x * blockDim.x + threadIdx.x;
    if (e >= E) return;

    const float dx = *dxp;
    const float dy = *dyp;
    const float nxf = (float)(*nxp);
    const float nyf = (float)(*nyp);

    const float p1x = 0.5f * (x1l[e] + x1r[e]);
    const float p1y = 0.5f * (y1l[e] + y1r[e]);
    const float p2x = 0.5f * (x2l[e] + x2r[e]);
    const float p2y = 0.5f * (y2l[e] + y2r[e]);
    const float dvx = p2x - p1x;
    const float dvy = p2y - p1y;
    const float L   = sqrtf(dvx * dvx + dvy * dvy);

    const float sigma     = (*trp) * 0.3f / (2.0f * 2.3548200450309493f);
    const float inv_sigma = 1.0f / sigma;
    const float norm      = 0.3989422804014327f * inv_sigma;
    const float tc        = 0.5f * L + 0.5f * tof[e];
    const float step      = L * INV_NSAMP;

    const float dfx = dvx * INV_NSAMP / dx;
    const float dfy = dvy * INV_NSAMP / dy;
    const float fx0 = (p1x + dvx * (0.5f * INV_NSAMP)) / dx + 0.5f * nxf - 0.5f;
    const float fy0 = (p1y + dvy * (0.5f * INV_NSAMP)) / dy + 0.5f * nyf - 0.5f;
    const float dz  = step * inv_sigma;
    const float z0  = (step * 0.5f - tc) * inv_sigma;

    int i_lo = (int)floorf((-ZCUT - z0) / dz);
    int i_hi = (int)ceilf (( ZCUT - z0) / dz);
    if (i_lo < 0)         i_lo = 0;
    if (i_lo > NSAMP - 1) i_lo = NSAMP - 1;
    if (i_hi < 0)         i_hi = 0;
    if (i_hi > NSAMP - 1) i_hi = NSAMP - 1;

    const bool steep = fabsf(dvy) > fabsf(dvx);
    const float a0 = (steep ? fy0 : fx0) + (float)PADX;
    const float da = steep ? dfy : dfx;
    const float b0 = (steep ? fx0 : fy0) + (float)PADY;
    const float db = steep ? dfx : dfy;

    unsigned packed = (unsigned)i_lo | ((unsigned)i_hi << 8) |
                      (steep ? 0x80000000u : 0u);

    g_tA[e] = make_float4(a0, da, b0, db);
    g_tB[e] = make_float4(z0, dz, norm * step, __uint_as_float(packed));

    // Locality key: 6-bit line angle (mod pi) + 3+3-bit TOF-center cell.
    float th = atan2f(dvy, dvx);                      // [-pi, pi]
    if (th < 0.0f) th += 3.14159265358979f;           // mod pi
    int a = (int)(th * (64.0f / 3.14159265358979f));
    a = min(max(a, 0), 63);
    const float tfrac = tc / L;
    const float ccx = p1x + dvx * tfrac;              // footprint center (mm)
    const float ccy = p1y + dvy * tfrac;
    int cx = (int)((ccx + 256.0f) * (1.0f / 64.0f));
    int cy = (int)((ccy + 256.0f) * (1.0f / 64.0f));
    cx = min(max(cx, 0), 7);
    cy = min(max(cy, 0), 7);
    const int key = (a << 6) | (cx << 3) | cy;
    g_key[e] = key;
    atomicAdd(&g_hist[key], 1);
}

// ---- K3: exclusive prefix sum over NKEY buckets (one block, 1024 thr) ----
__global__ void scan_kernel()
{
    __shared__ int sm[1024];
    const int tid = threadIdx.x;
    int v0 = g_hist[tid * 4 + 0];
    int v1 = g_hist[tid * 4 + 1];
    int v2 = g_hist[tid * 4 + 2];
    int v3 = g_hist[tid * 4 + 3];
    const int s = v0 + v1 + v2 + v3;
    sm[tid] = s;
    __syncthreads();
    int acc = s;
    for (int off = 1; off < 1024; off <<= 1) {
        int t = (tid >= off) ? sm[tid - off] : 0;
        __syncthreads();
        acc += t;
        sm[tid] = acc;
        __syncthreads();
    }
    const int base = acc - s;               // exclusive prefix of this thread
    g_off[tid * 4 + 0] = base;
    g_off[tid * 4 + 1] = base + v0;
    g_off[tid * 4 + 2] = base + v0 + v1;
    g_off[tid * 4 + 3] = base + v0 + v1 + v2;
}

// ---- K4: scatter params into sorted order ----
__global__ void scatter_kernel(int E)
{
    const int e = blockIdx.x * blockDim.x + threadIdx.x;
    if (e >= E) return;
    const int key = g_key[e];
    const int pos = atomicAdd(&g_off[key], 1);
    g_pA[pos]  = g_tA[e];
    g_pB[pos]  = g_tB[e];
    g_eid[pos] = e;
}

// ---- K5: project (R8 loop; sorted params; scattered final store) ----
__global__ void __launch_bounds__(128)
project_kernel(float* __restrict__ out, int E)
{
    const int g = blockIdx.x * blockDim.x + threadIdx.x;
    int       e = g >> 3;                 // sorted event slot
    const int h = g & 7;
    const bool valid = (e < E);
    if (!valid) e = E - 1;

    const float4 pA = g_pA[e];
    const float4 pB = g_pB[e];

    const unsigned packed = __float_as_uint(pB.w);
    const int  i_lo  = (int)(packed & 0xffu);
    const int  i_hi  = (int)((packed >> 8) & 0xffu);
    const bool steep = (packed & 0x80000000u) != 0u;

    const h4* __restrict__ base = steep ? g_padhT : g_padh;

    const float kexp = -0.72134752044448f;     // -0.5 * log2(e)
    const float da = pA.y, db = pA.w;
    const float dz = pB.y;

    const int   i0  = i_lo + h;
    const float fi0 = (float)i0;
    float u = fmaf(fi0, da, pA.x);
    float v = fmaf(fi0, db, pA.z);
    const float zs = fmaf(fi0, dz, pB.x);
    const float kd = kexp * dz;
    float q   = (kexp * zs) * zs;
    float dq  = kd * fmaf(64.0f, dz, 16.0f * zs);
    const float ddq = 128.0f * kd * dz;
    const float du = 8.0f * da;
    const float dv = 8.0f * db;

    const int n = (i_hi - i0 >= 0) ? ((i_hi - i0) >> 3) + 1 : 0;

    float acc = 0.0f;

    #pragma unroll 4
    for (int it = 0; it < n; ++it) {
        const int iu = (int)u;
        const int iv = (int)v;
        const float wu = u - (float)iu;
        const float wv = v - (float)iv;

        const h4 c = base[iv * PAD_W + iu];

        const __half2 wu2 = __floats2half2_rn(wu, wu);
        const __half2 l2  = __hfma2(wu2, __hsub2(c.hi, c.lo), c.lo);

        const float l0 = __low2float(l2);
        const float l1 = __high2float(l2);
        const float val = fmaf(wv, l1 - l0, l0);

        float w;
        asm("ex2.approx.ftz.f32 %0, %1;" : "=f"(w) : "f"(q));
        acc = fmaf(w, val, acc);

        u += du; v += dv;
        q += dq; dq += ddq;
    }

    acc += __shfl_xor_sync(0xffffffffu, acc, 1);
    acc += __shfl_xor_sync(0xffffffffu, acc, 2);
    acc += __shfl_xor_sync(0xffffffffu, acc, 4);

    if (valid && h == 0)
        out[g_eid[e]] = acc * pB.z;
}

extern "C" void kernel_launch(void* const* d_in, const int* in_sizes, int n_in,
                              void* d_out, int out_size)
{
    const float* image = (const float*)d_in[0];
    const float* tof   = (const float*)d_in[1];
    const float* x1l   = (const float*)d_in[2];
    const float* y1l   = (const float*)d_in[3];
    const float* x1r   = (const float*)d_in[4];
    const float* y1r   = (const float*)d_in[5];
    const float* x2l   = (const float*)d_in[6];
    const float* y2l   = (const float*)d_in[7];
    const float* x2r   = (const float*)d_in[8];
    const float* y2r   = (const float*)d_in[9];
    const float* trp   = (const float*)d_in[10];
    const float* dxp   = (const float*)d_in[11];
    const float* dyp   = (const float*)d_in[12];
    const int*   nxp   = (const int*)d_in[13];
    const int*   nyp   = (const int*)d_in[14];

    const int E = in_sizes[1];

    const int zero_blocks = (NKEY + 255) / 256;
    tiles_kernel<<<NTILE * NTILE + zero_blocks, 256>>>(image, nxp, nyp);

    keys_kernel<<<(E + 255) / 256, 256>>>(tof, x1l, y1l, x1r, y1r,
                                          x2l, y2l, x2r, y2r,
                                          trp, dxp, dyp, nxp, nyp, E);

    scan_kernel<<<1, 1024>>>();

    scatter_kernel<<<(E + 255) / 256, 256>>>(E);

    const int threads = 128;
    const long long total = (long long)E * SPLIT;
    const int blocks = (int)((total + threads - 1) / threads);
    project_kernel<<<blocks, threads>>>((float*)d_out, E);
}

// round 16
// speedup vs baseline: 1.4824x; 1.4824x over previous
#include <cuda_runtime.h>
#include <cuda_fp16.h>
#include <math.h>

// ---------------------------------------------------------------------------
// TOF PET forward projection, 6-layout (axis + diagonal skew) image cache.
//  prep (PDL primary): smem-tiled build of corner-packed fp16 image in
//    row-major, transposed, and 4 skewed (v−u / v+u) layouts + event params.
//  project (PDL secondary): 8 threads/event, per-event layout chosen to
//    minimize row drift |db − s*da|; loop body identical cost to R8.
// ---------------------------------------------------------------------------

#define PAD_W   384
#define SKH     768            // skew-layout row count
#define PADX    40
#define PADY    40
#define NSAMP   256
#define INV_NSAMP (1.0f / 256.0f)
#define ZCUT    3.6f           // tail 2*Q(3.6) ~ 3.2e-4
#define SPLIT   8
#define EMAX    160000
#define NTILE   18

struct __align__(8) h4 { __half2 lo, hi; };

// Zero-initialized; unwritten entries stay zero (outside-image masking).
__device__ h4 g_p0[PAD_W * PAD_W];   // non-steep, row = v
__device__ h4 g_pm[SKH * PAD_W];     // non-steep, row = v - u (+383)
__device__ h4 g_pp[SKH * PAD_W];     // non-steep, row = v + u
__device__ h4 g_q0[PAD_W * PAD_W];   // steep (u,v)=(y,x), row = v
__device__ h4 g_qm[SKH * PAD_W];     // steep, row = v - u (+383)
__device__ h4 g_qp[SKH * PAD_W];     // steep, row = v + u

__device__ float4 g_pA[EMAX];   // a0(+PADX), da, b0(+PADY), db
__device__ float4 g_pB[EMAX];   // z0, dz, scale, bits

__global__ void prep_kernel(const float* __restrict__ img,
               const float* __restrict__ tof,
               const float* __restrict__ x1l, const float* __restrict__ y1l,
               const float* __restrict__ x1r, const float* __restrict__ y1r,
               const float* __restrict__ x2l, const float* __restrict__ y2l,
               const float* __restrict__ x2r, const float* __restrict__ y2r,
               const float* __restrict__ trp,
               const float* __restrict__ dxp, const float* __restrict__ dyp,
               const int* __restrict__ nxp, const int* __restrict__ nyp,
               int E)
{
    asm volatile("griddepcontrol.launch_dependents;");

    const int nx = *nxp;
    const int ny = *nyp;
    const int tid = threadIdx.x;
    const int blk = blockIdx.x;
    const int NTILES = NTILE * NTILE;

    if (blk < NTILES) {
        __shared__ float sm[17][18];
        const int ty = blk / NTILE;
        const int tx = blk - ty * NTILE;
        const int ixs = -1 + tx * 16;          // tile origin (image coords)
        const int iys = -1 + ty * 16;

        for (int k = tid; k < 17 * 17; k += 256) {
            const int r = k / 17;
            const int c = k - r * 17;
            const int y = iys + r;
            const int x = ixs + c;
            sm[r][c] = (x >= 0 && x < nx && y >= 0 && y < ny)
                       ? img[y * nx + x] : 0.0f;
        }
        __syncthreads();

        // Non-steep pack at cell (lx, ly): lo=(v, v+1) at u; hi same at u+1.
        auto packN = [&](int lx, int ly) {
            h4 o;
            o.lo = __floats2half2_rn(sm[ly][lx],     sm[ly + 1][lx]);
            o.hi = __floats2half2_rn(sm[ly][lx + 1], sm[ly + 1][lx + 1]);
            return o;
        };
        // Steep pack ((u,v)=(y,x)): lo=(v, v+1)=(x, x+1) at u=y; hi at y+1.
        auto packT = [&](int lx, int ly) {
            h4 o;
            o.lo = __floats2half2_rn(sm[ly][lx],     sm[ly][lx + 1]);
            o.hi = __floats2half2_rn(sm[ly + 1][lx], sm[ly + 1][lx + 1]);
            return o;
        };

        // ---- base layouts (coalesced natural mapping) ----
        {
            const int ly = tid >> 4, lx = tid & 15;
            const int u = ixs + lx + PADX, v = iys + ly + PADY;
            g_p0[v * PAD_W + u] = packN(lx, ly);
        }
        {
            const int lx = tid >> 4, ly = tid & 15;   // fast axis = y
            const int u = iys + ly + PADY, v = ixs + lx + PADX;
            g_q0[v * PAD_W + u] = packT(lx, ly);
        }

        // ---- non-steep skews: (u,v) = (x+PADX, y+PADY) ----
        {   // pm: row = v-u const along runs -> vl = (d + ul) & 15
            const int d = tid >> 4, ul = tid & 15;
            const int vl = (d + ul) & 15;
            const int u = ixs + ul + PADX, v = iys + vl + PADY;
            g_pm[(v - u + 383) * PAD_W + u] = packN(ul, vl);
        }
        {   // pp: row = v+u const along runs -> vl = (d - ul) & 15
            const int d = tid >> 4, ul = tid & 15;
            const int vl = (d - ul) & 15;
            const int u = ixs + ul + PADX, v = iys + vl + PADY;
            g_pp[(v + u) * PAD_W + u] = packN(ul, vl);
        }

        // ---- steep skews: (u,v) = (y+PADY, x+PADX) ----
        {   // qm: row = v-u = x-y const -> ixl = (d + ul) & 15, ul = y_local
            const int d = tid >> 4, ul = tid & 15;
            const int xl = (d + ul) & 15;
            const int u = iys + ul + PADY, v = ixs + xl + PADX;
            g_qm[(v - u + 383) * PAD_W + u] = packT(xl, ul);
        }
        {   // qp: row = v+u = x+y const -> ixl = (d - ul) & 15
            const int d = tid >> 4, ul = tid & 15;
            const int xl = (d - ul) & 15;
            const int u = iys + ul + PADY, v = ixs + xl + PADX;
            g_qp[(v + u) * PAD_W + u] = packT(xl, ul);
        }
        return;
    }

    // ---- event block: per-event parameter precompute ----
    const int e = (blk - NTILES) * 256 + tid;
    if (e >= E) return;

    const float dx = *dxp;
    const float dy = *dyp;
    const float nxf = (float)nx;
    const float nyf = (float)ny;

    const float p1x = 0.5f * (x1l[e] + x1r[e]);
    const float p1y = 0.5f * (y1l[e] + y1r[e]);
    const float p2x = 0.5f * (x2l[e] + x2r[e]);
    const float p2y = 0.5f * (y2l[e] + y2r[e]);
    const float dvx = p2x - p1x;
    const float dvy = p2y - p1y;
    const float L   = sqrtf(dvx * dvx + dvy * dvy);

    const float sigma     = (*trp) * 0.3f / (2.0f * 2.3548200450309493f);
    const float inv_sigma = 1.0f / sigma;
    const float norm      = 0.3989422804014327f * inv_sigma;
    const float tc        = 0.5f * L + 0.5f * tof[e];
    const float step      = L * INV_NSAMP;

    const float dfx = dvx * INV_NSAMP / dx;
    const float dfy = dvy * INV_NSAMP / dy;
    const float fx0 = (p1x + dvx * (0.5f * INV_NSAMP)) / dx + 0.5f * nxf - 0.5f;
    const float fy0 = (p1y + dvy * (0.5f * INV_NSAMP)) / dy + 0.5f * nyf - 0.5f;
    const float dz  = step * inv_sigma;          // > 0 (L > 0)
    const float z0  = (step * 0.5f - tc) * inv_sigma;

    int i_lo = (int)floorf((-ZCUT - z0) / dz);
    int i_hi = (int)ceilf (( ZCUT - z0) / dz);
    if (i_lo < 0)         i_lo = 0;
    if (i_lo > NSAMP - 1) i_lo = NSAMP - 1;
    if (i_hi < 0)         i_hi = 0;
    if (i_hi > NSAMP - 1) i_hi = NSAMP - 1;

    const bool steep = fabsf(dvy) > fabsf(dvx);
    const float a0 = (steep ? fy0 : fx0) + (float)PADX;
    const float da = steep ? dfy : dfx;
    const float b0 = (steep ? fx0 : fy0) + (float)PADY;
    const float db = steep ? dfx : dfy;

    // Diagonal skew selection: s = round(db/da) in {-1, 0, +1} minimizes
    // the row-drift |db - s*da| of the chosen layout.
    const int s = (int)rintf(db / da);     // |db| <= |da| -> s in {-1,0,1}

    unsigned packed = (unsigned)i_lo | ((unsigned)i_hi << 8) |
                      ((unsigned)(s + 1) << 16) |
                      (steep ? 0x80000000u : 0u);

    g_pA[e] = make_float4(a0, da, b0, db);
    g_pB[e] = make_float4(z0, dz, norm * step, __uint_as_float(packed));
}

__global__ void __launch_bounds__(128)
project_kernel(float* __restrict__ out, int E)
{
    asm volatile("griddepcontrol.wait;" ::: "memory");

    const int g = blockIdx.x * blockDim.x + threadIdx.x;
    int       e = g >> 3;
    const int h = g & 7;
    const bool valid = (e < E);
    if (!valid) e = E - 1;

    const float4 pA = g_pA[e];
    const float4 pB = g_pB[e];

    const unsigned packed = __float_as_uint(pB.w);
    const int  i_lo  = (int)(packed & 0xffu);
    const int  i_hi  = (int)((packed >> 8) & 0xffu);
    const int  s     = (int)((packed >> 16) & 3u) - 1;   // -1, 0, +1
    const bool steep = (packed & 0x80000000u) != 0u;

    // Layout select; fold the pm/qm row offset (+383 rows) into the base.
    const h4* __restrict__ base;
    if (steep) base = (s == 0) ? g_q0 : (s == 1) ? g_qm : g_qp;
    else       base = (s == 0) ? g_p0 : (s == 1) ? g_pm : g_pp;
    if (s == 1) base += 383 * PAD_W;
    const int cmul = 1 - s * PAD_W;        // idx = iv*384 + iu*cmul

    const float kexp = -0.72134752044448f; // -0.5 * log2(e)
    const float da = pA.y, db = pA.w;
    const float dz = pB.y;

    const int   i0  = i_lo + h;
    const float fi0 = (float)i0;
    float u = fmaf(fi0, da, pA.x);
    float v = fmaf(fi0, db, pA.z);
    const float zs = fmaf(fi0, dz, pB.x);
    const float kd = kexp * dz;
    float q   = (kexp * zs) * zs;
    float dq  = kd * fmaf(64.0f, dz, 16.0f * zs);
    const float ddq = 128.0f * kd * dz;
    const float du = 8.0f * da;
    const float dv = 8.0f * db;

    const int n = (i_hi - i0 >= 0) ? ((i_hi - i0) >> 3) + 1 : 0;

    float acc = 0.0f;

    #pragma unroll 4
    for (int it = 0; it < n; ++it) {
        const int iu = (int)u;             // u,v > 0: trunc == floor
        const int iv = (int)v;
        const float wu = u - (float)iu;
        const float wv = v - (float)iv;

        const h4 c = base[iv * PAD_W + iu * cmul];

        const __half2 wu2 = __floats2half2_rn(wu, wu);
        const __half2 l2  = __hfma2(wu2, __hsub2(c.hi, c.lo), c.lo);

        const float l0 = __low2float(l2);
        const float l1 = __high2float(l2);
        const float val = fmaf(wv, l1 - l0, l0);

        float w;
        asm("ex2.approx.ftz.f32 %0, %1;" : "=f"(w) : "f"(q));
        acc = fmaf(w, val, acc);

        u += du; v += dv;
        q += dq; dq += ddq;
    }

    acc += __shfl_xor_sync(0xffffffffu, acc, 1);
    acc += __shfl_xor_sync(0xffffffffu, acc, 2);
    acc += __shfl_xor_sync(0xffffffffu, acc, 4);

    if (valid && h == 0)
        out[e] = acc * pB.z;
}

extern "C" void kernel_launch(void* const* d_in, const int* in_sizes, int n_in,
                              void* d_out, int out_size)
{
    const float* image = (const float*)d_in[0];
    const float* tof   = (const float*)d_in[1];
    const float* x1l   = (const float*)d_in[2];
    const float* y1l   = (const float*)d_in[3];
    const float* x1r   = (const float*)d_in[4];
    const float* y1r   = (const float*)d_in[5];
    const float* x2l   = (const float*)d_in[6];
    const float* y2l   = (const float*)d_in[7];
    const float* x2r   = (const float*)d_in[8];
    const float* y2r   = (const float*)d_in[9];
    const float* trp   = (const float*)d_in[10];
    const float* dxp   = (const float*)d_in[11];
    const float* dyp   = (const float*)d_in[12];
    const int*   nxp   = (const int*)d_in[13];
    const int*   nyp   = (const int*)d_in[14];

    const int E = in_sizes[1];

    const int tile_blocks  = NTILE * NTILE;
    const int event_blocks = (E + 255) / 256;
    prep_kernel<<<tile_blocks + event_blocks, 256>>>(image, tof,
                                                     x1l, y1l, x1r, y1r,
                                                     x2l, y2l, x2r, y2r,
                                                     trp, dxp, dyp, nxp, nyp, E);

    const int threads = 128;
    const long long total = (long long)E * SPLIT;
    const int blocks = (int)((total + threads - 1) / threads);

    cudaLaunchConfig_t cfg = {};
    cfg.gridDim  = dim3((unsigned)blocks, 1, 1);
    cfg.blockDim = dim3((unsigned)threads, 1, 1);
    cfg.dynamicSmemBytes = 0;
    cfg.stream = 0;

    cudaLaunchAttribute attr[1];
    attr[0].id = cudaLaunchAttributeProgrammaticStreamSerialization;
    attr[0].val.programmaticStreamSerializationAllowed = 1;
    cfg.attrs = attr;
    cfg.numAttrs = 1;

    cudaLaunchKernelEx(&cfg, project_kernel, (float*)d_out, E);
}